// round 1
// baseline (speedup 1.0000x reference)
#include <cuda_runtime.h>
#include <math.h>

// Problem shape (fixed by the dataset): n=8192, k=128, h=128
#define NMAX 8192
#define KDIM 128

// Scratch (no cudaMalloc allowed)
__device__ float g_M[NMAX * KDIM];   // 4 MB: M = A @ C
__device__ float g_d[NMAX];          // row sums of A
__device__ float g_col[KDIM];        // column sums of M
__device__ float g_diag[KDIM];       // diag(C^T A C)
__device__ float g_sA;               // sum(A)
__device__ float g_hpart;            // sum_i d_i * ||H_i||^2

// ---------- packed f32x2 helpers ----------
__device__ __forceinline__ unsigned long long pack2(float x, float y) {
    unsigned long long r;
    asm("mov.b64 %0, {%1, %2};" : "=l"(r) : "f"(x), "f"(y));
    return r;
}
__device__ __forceinline__ void unpack2(unsigned long long v, float& x, float& y) {
    asm("mov.b64 {%0, %1}, %2;" : "=f"(x), "=f"(y) : "l"(v));
}
__device__ __forceinline__ void fma2(unsigned long long& acc, unsigned long long a,
                                     unsigned long long b) {
    asm("fma.rn.f32x2 %0, %1, %2, %0;" : "+l"(acc) : "l"(a), "l"(b));
}

// ---------- init ----------
__global__ void k_init(int n) {
    int i = blockIdx.x * blockDim.x + threadIdx.x;
    if (i < n) g_d[i] = 0.0f;
    if (i < KDIM) { g_col[i] = 0.0f; g_diag[i] = 0.0f; }
    if (i == 0) { g_sA = 0.0f; g_hpart = 0.0f; }
}

// ---------- fused GEMM (M = A@C) + row sums of A ----------
// BM=64 rows per block, BK=32, BN=KDIM=128 cols. 128 threads, 8x8 microtile.
#define BM 64
#define BK 32
#define BN 128

__global__ void __launch_bounds__(128) k_gemm(const float* __restrict__ A,
                                              const float* __restrict__ C, int n) {
    __shared__ float As[BK][BM + 4];   // [l][row], pad keeps 16B alignment + bank spread
    __shared__ float Cs[BK][BN + 4];   // [l][j]

    const int tid = threadIdx.x;
    const int blockRow = blockIdx.x * BM;
    const int tr = tid / 16;           // 0..7  -> rows tr*8..tr*8+7
    const int tc = tid % 16;           // 0..15 -> cols tc*8..tc*8+7

    // A-tile load mapping: 2048 floats = 512 float4 / 128 threads = 4 each
    const int arow = tid / 8;          // base row (0..15), +16 per iteration
    const int acol = (tid % 8) * 4;    // float offset within the 32-wide tile

    unsigned long long acc[8][4];      // 8 rows x 4 packed col-pairs, fp32x2
#pragma unroll
    for (int i = 0; i < 8; i++)
#pragma unroll
        for (int j = 0; j < 4; j++) acc[i][j] = 0ULL;

    float dsum[4] = {0.f, 0.f, 0.f, 0.f};

    for (int k0 = 0; k0 < n; k0 += BK) {
        // Load A tile [BM x BK] -> As transposed [l][row]; fuse row-sum accumulation
#pragma unroll
        for (int it = 0; it < 4; ++it) {
            int r = arow + 16 * it;
            const float4 v = *reinterpret_cast<const float4*>(
                &A[(size_t)(blockRow + r) * n + k0 + acol]);
            dsum[it] += (v.x + v.y) + (v.z + v.w);
            As[acol + 0][r] = v.x;
            As[acol + 1][r] = v.y;
            As[acol + 2][r] = v.z;
            As[acol + 3][r] = v.w;
        }
        // Load C tile [BK x BN]
#pragma unroll
        for (int it = 0; it < 8; ++it) {
            int l = 4 * it + tid / 32;
            int j4 = (tid % 32) * 4;
            *reinterpret_cast<float4*>(&Cs[l][j4]) =
                *reinterpret_cast<const float4*>(&C[(size_t)(k0 + l) * BN + j4]);
        }
        __syncthreads();

#pragma unroll 4
        for (int kk = 0; kk < BK; ++kk) {
            const float4 a0 = *reinterpret_cast<const float4*>(&As[kk][tr * 8]);
            const float4 a1 = *reinterpret_cast<const float4*>(&As[kk][tr * 8 + 4]);
            const float4 b0 = *reinterpret_cast<const float4*>(&Cs[kk][tc * 8]);
            const float4 b1 = *reinterpret_cast<const float4*>(&Cs[kk][tc * 8 + 4]);
            unsigned long long bp[4] = {pack2(b0.x, b0.y), pack2(b0.z, b0.w),
                                        pack2(b1.x, b1.y), pack2(b1.z, b1.w)};
            float a8[8] = {a0.x, a0.y, a0.z, a0.w, a1.x, a1.y, a1.z, a1.w};
#pragma unroll
            for (int i = 0; i < 8; i++) {
                unsigned long long ap = pack2(a8[i], a8[i]);
#pragma unroll
                for (int j = 0; j < 4; j++) fma2(acc[i][j], ap, bp[j]);
            }
        }
        __syncthreads();
    }

    // Write M tile
#pragma unroll
    for (int i = 0; i < 8; i++) {
        int grow = blockRow + tr * 8 + i;
        float o[8];
#pragma unroll
        for (int j = 0; j < 4; j++) unpack2(acc[i][j], o[2 * j], o[2 * j + 1]);
        float4 v0 = make_float4(o[0], o[1], o[2], o[3]);
        float4 v1 = make_float4(o[4], o[5], o[6], o[7]);
        *reinterpret_cast<float4*>(&g_M[(size_t)grow * KDIM + tc * 8]) = v0;
        *reinterpret_cast<float4*>(&g_M[(size_t)grow * KDIM + tc * 8 + 4]) = v1;
    }
    // Row sums (8 threads contribute per row)
#pragma unroll
    for (int it = 0; it < 4; ++it)
        atomicAdd(&g_d[blockRow + arow + 16 * it], dsum[it]);
}

// ---------- reductions over M, C, H ----------
__global__ void k_reduce(const float* __restrict__ C, const float* __restrict__ H, int n) {
    const int tid = threadIdx.x;     // 256 threads
    const int j = tid & (KDIM - 1);  // column 0..127
    const int rg = tid >> 7;         // 0/1 row group
    const int rows_per_block = n / gridDim.x;
    const int base = blockIdx.x * rows_per_block;

    float colacc = 0.f, diagacc = 0.f, hacc = 0.f, dacc = 0.f;
    for (int r = rg; r < rows_per_block; r += 2) {
        int i = base + r;
        float m = g_M[(size_t)i * KDIM + j];
        float c = C[(size_t)i * KDIM + j];
        float hv = H[(size_t)i * KDIM + j];
        float di = g_d[i];
        colacc += m;
        diagacc += c * m;
        hacc += di * hv * hv;
        if (j == 0) dacc += di;
    }

    __shared__ float s1[256], s2[256];
    s1[tid] = colacc; s2[tid] = diagacc;
    __syncthreads();
    if (tid < KDIM) {
        atomicAdd(&g_col[j], s1[tid] + s1[tid + KDIM]);
        atomicAdd(&g_diag[j], s2[tid] + s2[tid + KDIM]);
    }
    __syncthreads();
    s1[tid] = hacc; s2[tid] = dacc;
    __syncthreads();
    for (int s = 128; s > 0; s >>= 1) {
        if (tid < s) { s1[tid] += s1[tid + s]; s2[tid] += s2[tid + s]; }
        __syncthreads();
    }
    if (tid == 0) {
        atomicAdd(&g_hpart, s1[0]);
        atomicAdd(&g_sA, s2[0]);
    }
}

// ---------- final scalar epilogue ----------
__global__ void k_final(const float* papra, const int* flag, float* out, int out_size) {
    const int tid = threadIdx.x;  // 128 threads
    float sA = g_sA;
    float t = g_diag[tid] * log2f(g_col[tid] / sA + 1e-40f);
    __shared__ float s[128];
    s[tid] = t;
    __syncthreads();
    for (int st = 64; st > 0; st >>= 1) {
        if (tid < st) s[tid] += s[tid + st];
        __syncthreads();
    }
    if (tid == 0) {
        float total = s[0] / sA;
        float hp = g_hpart;
        int fl = flag ? *flag : 20;
        float pw = papra ? *papra : 1.0f;
        if (fl > 10) total += pw * hp;
        out[0] = total;
        if (out_size > 1) out[1] = hp;
    }
}

extern "C" void kernel_launch(void* const* d_in, const int* in_sizes, int n_in,
                              void* d_out, int out_size) {
    const float* A = (const float*)d_in[0];
    const float* C = (const float*)d_in[1];
    const float* H = (const float*)d_in[2];
    const float* papra = (n_in > 3) ? (const float*)d_in[3] : nullptr;
    const int* flag = (n_in > 4) ? (const int*)d_in[4] : nullptr;

    int n = (int)(sqrt((double)in_sizes[0]) + 0.5);  // 8192

    k_init<<<(n + 255) / 256, 256>>>(n);
    k_gemm<<<n / BM, 128>>>(A, C, n);
    k_reduce<<<64, 256>>>(C, H, n);
    k_final<<<1, 128>>>(papra, flag, (float*)d_out, out_size);
}

// round 3
// speedup vs baseline: 7.7311x; 7.7311x over previous
#include <cuda_runtime.h>
#include <cuda_bf16.h>
#include <math.h>
#include <stdint.h>

// Fixed problem shape: n=8192, k=128, h=128
#define N_FIX 8192
#define KDIM 128
#define BM 64
#define BK 32
#define NITER (N_FIX / BK)      // 256
#define STAGES 4
#define STAGE_BYTES 16384       // 8KB A (64x32 fp32) + 8KB B (32x128 bf16)
#define SMEM_BYTES (STAGES * STAGE_BYTES)

// ---------------- device scratch (no cudaMalloc allowed) ----------------
__device__ __align__(16) __nv_bfloat16 g_Cb[(size_t)N_FIX * KDIM];  // bf16 copy of C
__device__ float g_d[N_FIX];      // row sums of A (exact fp32)
__device__ float g_col[KDIM];     // column sums of M = A@C
__device__ float g_diag[KDIM];    // diag(C^T A C)
__device__ float g_sA;
__device__ float g_hpart;

// ---------------- helpers ----------------
__device__ __forceinline__ uint32_t smem_u32(const void* p) {
    uint32_t a;
    asm("{ .reg .u64 t; cvta.to.shared.u64 t, %1; cvt.u32.u64 %0, t; }" : "=r"(a) : "l"(p));
    return a;
}
__device__ __forceinline__ void cp16(uint32_t saddr, const void* gp) {
    unsigned long long g = __cvta_generic_to_global(gp);
    asm volatile("cp.async.cg.shared.global [%0], [%1], 16;" :: "r"(saddr), "l"(g) : "memory");
}
#define CP_COMMIT() asm volatile("cp.async.commit_group;" ::: "memory")
#define CP_WAIT2()  asm volatile("cp.async.wait_group 2;" ::: "memory")

__device__ __forceinline__ uint32_t cvt_bf2(float2 v) {
    uint32_t r;  // low = v.x, high = v.y
    asm("cvt.rn.bf16x2.f32 %0, %1, %2;" : "=r"(r) : "f"(v.y), "f"(v.x));
    return r;
}
__device__ __forceinline__ void ldmx4t(uint32_t& r0, uint32_t& r1, uint32_t& r2,
                                       uint32_t& r3, uint32_t addr) {
    asm volatile("ldmatrix.sync.aligned.m8n8.x4.trans.shared.b16 {%0,%1,%2,%3}, [%4];"
                 : "=r"(r0), "=r"(r1), "=r"(r2), "=r"(r3) : "r"(addr));
}
__device__ __forceinline__ void mma16816(float* d, const uint32_t* a, uint32_t b0,
                                         uint32_t b1) {
    asm volatile(
        "mma.sync.aligned.m16n8k16.row.col.f32.bf16.bf16.f32 "
        "{%0,%1,%2,%3}, {%4,%5,%6,%7}, {%8,%9}, {%0,%1,%2,%3};"
        : "+f"(d[0]), "+f"(d[1]), "+f"(d[2]), "+f"(d[3])
        : "r"(a[0]), "r"(a[1]), "r"(a[2]), "r"(a[3]), "r"(b0), "r"(b1));
}

// ---------------- init ----------------
__global__ void k_init() {
    int i = threadIdx.x;
    if (i < KDIM) { g_col[i] = 0.0f; g_diag[i] = 0.0f; }
    if (i == 0) { g_sA = 0.0f; g_hpart = 0.0f; }
}

// ---------------- convert C (fp32) -> g_Cb (bf16), same layout ----------------
__global__ void __launch_bounds__(256) k_prep(const float* __restrict__ C) {
    size_t base = ((size_t)blockIdx.x * 256 + threadIdx.x) * 16;
    const float4* src = reinterpret_cast<const float4*>(C + base);
    uint32_t o[8];
#pragma unroll
    for (int q = 0; q < 4; ++q) {
        float4 v = __ldg(&src[q]);
        o[q * 2 + 0] = cvt_bf2(make_float2(v.x, v.y));
        o[q * 2 + 1] = cvt_bf2(make_float2(v.z, v.w));
    }
    uint4* dst = reinterpret_cast<uint4*>(g_Cb + base);
    dst[0] = make_uint4(o[0], o[1], o[2], o[3]);
    dst[1] = make_uint4(o[4], o[5], o[6], o[7]);
}

// ---------------- main GEMM: M = A@C via mma.sync, fused reductions ----------------
__global__ void __launch_bounds__(256) k_gemm(const float* __restrict__ A,
                                              const float* __restrict__ C) {
    extern __shared__ __align__(1024) char smem[];
    __shared__ float scol[KDIM], sdiag[KDIM];

    const int tid = threadIdx.x, lane = tid & 31, wid = tid >> 5;
    const int wm = wid & 3, wn = wid >> 2;           // 4 M-warps x 2 N-warps
    const int blockRow = blockIdx.x * BM;
    const uint32_t su = smem_u32(smem);

    if (tid < KDIM) { scol[tid] = 0.0f; sdiag[tid] = 0.0f; }

    // ---- cp.async chunk mapping (2 A-chunks + 2 B-chunks per thread) ----
    // A tile: 64 rows x 32 fp32, row = 128B = 8 chunks; swizzle: ^(r&7)<<4
    // B tile: 32 rows x 128 bf16, row = 256B = 16 chunks; swizzle: ^(k&7)<<4
    const int chA0 = tid, chA1 = tid + 256;
    const int rA0 = chA0 >> 3, cA0 = chA0 & 7;
    const int rA1 = chA1 >> 3, cA1 = chA1 & 7;
    const uint32_t soA0 = (uint32_t)(chA0 * 16) ^ ((rA0 & 7) << 4);
    const uint32_t soA1 = (uint32_t)(chA1 * 16) ^ ((rA1 & 7) << 4);
    const float* gA0 = A + (size_t)(blockRow + rA0) * N_FIX + cA0 * 4;
    const float* gA1 = A + (size_t)(blockRow + rA1) * N_FIX + cA1 * 4;

    const int kB0 = chA0 >> 4, cB0 = chA0 & 15;
    const int kB1 = chA1 >> 4, cB1 = chA1 & 15;
    const uint32_t soB0 = (uint32_t)(chA0 * 16) ^ ((kB0 & 7) << 4);
    const uint32_t soB1 = (uint32_t)(chA1 * 16) ^ ((kB1 & 7) << 4);
    const __nv_bfloat16* gB0 = g_Cb + (size_t)kB0 * KDIM + cB0 * 8;
    const __nv_bfloat16* gB1 = g_Cb + (size_t)kB1 * KDIM + cB1 * 8;

    // ---- fragment smem offsets ----
    const int r0 = wm * 16 + (lane >> 2);
    const int cb = (lane & 3) * 2;
    uint32_t aoff[2][4];
#pragma unroll
    for (int kq = 0; kq < 2; ++kq) {
        int cc = kq * 16 + cb;
#pragma unroll
        for (int q = 0; q < 4; ++q) {
            int rr = r0 + ((q & 1) ? 8 : 0);
            int c2 = cc + ((q & 2) ? 8 : 0);
            uint32_t off = (uint32_t)(rr * 128 + c2 * 4);
            aoff[kq][q] = off ^ ((rr & 7) << 4);
        }
    }
    uint32_t boff[4];
    {
        const int mM = lane >> 3, iR = lane & 7;
        const int kkb = (mM & 1) * 8 + iR;
#pragma unroll
        for (int g = 0; g < 4; ++g) {
            int nn = wn * 64 + g * 16 + (mM >> 1) * 8;
            uint32_t off = (uint32_t)(kkb * 256 + nn * 2);
            boff[g] = off ^ ((kkb & 7) << 4);
        }
    }

    float acc[8][4];
#pragma unroll
    for (int t = 0; t < 8; ++t)
#pragma unroll
        for (int e = 0; e < 4; ++e) acc[t][e] = 0.0f;
    float dr0 = 0.0f, dr1 = 0.0f;

    // ---- prologue: fill STAGES-1 stages ----
#pragma unroll
    for (int s = 0; s < STAGES - 1; ++s) {
        uint32_t sb = su + s * STAGE_BYTES;
        size_t kf = (size_t)s * BK;
        cp16(sb + soA0, gA0 + kf);
        cp16(sb + soA1, gA1 + kf);
        cp16(sb + 8192 + soB0, gB0 + kf * KDIM);
        cp16(sb + 8192 + soB1, gB1 + kf * KDIM);
        CP_COMMIT();
    }

    // ---- main loop ----
    for (int it = 0; it < NITER; ++it) {
        CP_WAIT2();
        __syncthreads();
        const char* stp = smem + (it & (STAGES - 1)) * STAGE_BYTES;
        const uint32_t bbase = su + (uint32_t)((it & (STAGES - 1)) * STAGE_BYTES) + 8192;

#pragma unroll
        for (int kq = 0; kq < 2; ++kq) {
            float2 fA[4];
#pragma unroll
            for (int q = 0; q < 4; ++q)
                fA[q] = *reinterpret_cast<const float2*>(stp + aoff[kq][q]);
            dr0 += (fA[0].x + fA[0].y) + (fA[2].x + fA[2].y);
            dr1 += (fA[1].x + fA[1].y) + (fA[3].x + fA[3].y);
            uint32_t ra[4];
#pragma unroll
            for (int q = 0; q < 4; ++q) ra[q] = cvt_bf2(fA[q]);

#pragma unroll
            for (int g = 0; g < 4; ++g) {
                uint32_t b0, b1, b2, b3;
                ldmx4t(b0, b1, b2, b3, bbase + kq * 4096 + boff[g]);
                mma16816(acc[2 * g], ra, b0, b1);
                mma16816(acc[2 * g + 1], ra, b2, b3);
            }
        }

        int nxt = it + (STAGES - 1);
        if (nxt < NITER) {
            uint32_t sb = su + (nxt & (STAGES - 1)) * STAGE_BYTES;
            size_t kf = (size_t)nxt * BK;
            cp16(sb + soA0, gA0 + kf);
            cp16(sb + soA1, gA1 + kf);
            cp16(sb + 8192 + soB0, gB0 + kf * KDIM);
            cp16(sb + 8192 + soB1, gB1 + kf * KDIM);
        }
        CP_COMMIT();
    }

    // ---- row sums of A (exact fp32; only wn==0 warps, no double count) ----
    if (wn == 0) {
        float s0 = dr0, s1 = dr1;
        s0 += __shfl_xor_sync(0xffffffffu, s0, 1);
        s0 += __shfl_xor_sync(0xffffffffu, s0, 2);
        s1 += __shfl_xor_sync(0xffffffffu, s1, 1);
        s1 += __shfl_xor_sync(0xffffffffu, s1, 2);
        if ((lane & 3) == 0) {
            g_d[blockRow + r0] = s0;
            g_d[blockRow + r0 + 8] = s1;
        }
    }

    // ---- fused epilogue: colsum(M) and diag = sum_i C[i][j]*M[i][j] ----
#pragma unroll
    for (int t = 0; t < 8; ++t) {
        const int cbase = wn * 64 + t * 8 + cb;
        const int row = blockRow + r0;
        float2 c0 = *reinterpret_cast<const float2*>(C + (size_t)row * KDIM + cbase);
        float2 c1 = *reinterpret_cast<const float2*>(C + (size_t)(row + 8) * KDIM + cbase);
        float cs0 = acc[t][0] + acc[t][2];
        float cs1 = acc[t][1] + acc[t][3];
        float ds0 = c0.x * acc[t][0] + c1.x * acc[t][2];
        float ds1 = c0.y * acc[t][1] + c1.y * acc[t][3];
#pragma unroll
        for (int o = 4; o <= 16; o <<= 1) {
            cs0 += __shfl_xor_sync(0xffffffffu, cs0, o);
            cs1 += __shfl_xor_sync(0xffffffffu, cs1, o);
            ds0 += __shfl_xor_sync(0xffffffffu, ds0, o);
            ds1 += __shfl_xor_sync(0xffffffffu, ds1, o);
        }
        if ((lane >> 2) == 0) {  // lanes 0..3
            atomicAdd(&scol[cbase], cs0);
            atomicAdd(&scol[cbase + 1], cs1);
            atomicAdd(&sdiag[cbase], ds0);
            atomicAdd(&sdiag[cbase + 1], ds1);
        }
    }
    __syncthreads();
    if (tid < KDIM) {
        atomicAdd(&g_col[tid], scol[tid]);
        atomicAdd(&g_diag[tid], sdiag[tid]);
    }
}

// ---------------- h_part + sA ----------------
__global__ void __launch_bounds__(256) k_hpart(const float* __restrict__ H) {
    const int tid = threadIdx.x;
    const int row = blockIdx.x * 128 + (tid >> 1);
    const int ch = (tid & 1) * 64;
    const float4* hp = reinterpret_cast<const float4*>(H + (size_t)row * KDIM + ch);
    float h2 = 0.0f;
#pragma unroll
    for (int q = 0; q < 16; ++q) {
        float4 v = __ldg(&hp[q]);
        h2 += v.x * v.x + v.y * v.y + v.z * v.z + v.w * v.w;
    }
    h2 += __shfl_xor_sync(0xffffffffu, h2, 1);
    float dval = 0.0f, hc = 0.0f;
    if ((tid & 1) == 0) {
        dval = g_d[row];
        hc = dval * h2;
    }
    __shared__ float s1[256], s2[256];
    s1[tid] = hc; s2[tid] = dval;
    __syncthreads();
    for (int s = 128; s > 0; s >>= 1) {
        if (tid < s) { s1[tid] += s1[tid + s]; s2[tid] += s2[tid + s]; }
        __syncthreads();
    }
    if (tid == 0) {
        atomicAdd(&g_hpart, s1[0]);
        atomicAdd(&g_sA, s2[0]);
    }
}

// ---------------- final scalar epilogue ----------------
__global__ void k_final(const float* papra, const int* flag, float* out, int out_size) {
    const int tid = threadIdx.x;  // 128 threads
    float sA = g_sA;
    float t = g_diag[tid] * log2f(g_col[tid] / sA + 1e-40f);
    __shared__ float s[128];
    s[tid] = t;
    __syncthreads();
    for (int st = 64; st > 0; st >>= 1) {
        if (tid < st) s[tid] += s[tid + st];
        __syncthreads();
    }
    if (tid == 0) {
        float total = s[0] / sA;
        float hp = g_hpart;
        int fl = flag ? *flag : 20;
        float pw = papra ? *papra : 1.0f;
        if (fl > 10) total += pw * hp;
        out[0] = total;
        if (out_size > 1) out[1] = hp;
    }
}

extern "C" void kernel_launch(void* const* d_in, const int* in_sizes, int n_in,
                              void* d_out, int out_size) {
    const float* A = (const float*)d_in[0];
    const float* C = (const float*)d_in[1];
    const float* H = (const float*)d_in[2];
    const float* papra = (n_in > 3) ? (const float*)d_in[3] : nullptr;
    const int* flag = (n_in > 4) ? (const int*)d_in[4] : nullptr;

    cudaFuncSetAttribute(k_gemm, cudaFuncAttributeMaxDynamicSharedMemorySize, SMEM_BYTES);

    k_init<<<1, 256>>>();
    k_prep<<<(N_FIX * KDIM) / (256 * 16), 256>>>(C);
    k_gemm<<<N_FIX / BM, 256, SMEM_BYTES>>>(A, C);
    k_hpart<<<N_FIX / 128, 256>>>(H);
    k_final<<<1, 128>>>(papra, flag, (float*)d_out, out_size);
}

// round 4
// speedup vs baseline: 7.7331x; 1.0003x over previous
#include <cuda_runtime.h>
#include <cuda_bf16.h>
#include <math.h>
#include <stdint.h>

// Fixed problem shape: n=8192, k=128, h=128
#define N_FIX 8192
#define KDIM 128
#define BM 64
#define BK 32
#define NITER (N_FIX / BK)      // 256
#define STAGES 4
#define STAGE_BYTES 16384       // 8KB A (64x32 fp32) + 8KB B (32x128 bf16)
#define SMEM_BYTES (STAGES * STAGE_BYTES)

// ---------------- device scratch (no cudaMalloc allowed) ----------------
__device__ __align__(16) __nv_bfloat16 g_Cb[(size_t)N_FIX * KDIM];  // bf16 copy of C
__device__ float g_d[N_FIX];      // row sums of A (exact fp32)
__device__ float g_col[KDIM];     // column sums of M = A@C
__device__ float g_diag[KDIM];    // diag(C^T A C)
__device__ float g_sA;
__device__ float g_hpart;

// ---------------- helpers ----------------
__device__ __forceinline__ uint32_t smem_u32(const void* p) {
    uint32_t a;
    asm("{ .reg .u64 t; cvta.to.shared.u64 t, %1; cvt.u32.u64 %0, t; }" : "=r"(a) : "l"(p));
    return a;
}
__device__ __forceinline__ void cp16(uint32_t saddr, const void* gp) {
    unsigned long long g = __cvta_generic_to_global(gp);
    asm volatile("cp.async.cg.shared.global [%0], [%1], 16;" :: "r"(saddr), "l"(g) : "memory");
}
#define CP_COMMIT() asm volatile("cp.async.commit_group;" ::: "memory")
#define CP_WAIT2()  asm volatile("cp.async.wait_group 2;" ::: "memory")

__device__ __forceinline__ uint32_t cvt_bf2(float2 v) {
    uint32_t r;  // low = v.x, high = v.y
    asm("cvt.rn.bf16x2.f32 %0, %1, %2;" : "=r"(r) : "f"(v.y), "f"(v.x));
    return r;
}
__device__ __forceinline__ void ldmx4t(uint32_t& r0, uint32_t& r1, uint32_t& r2,
                                       uint32_t& r3, uint32_t addr) {
    asm volatile("ldmatrix.sync.aligned.m8n8.x4.trans.shared.b16 {%0,%1,%2,%3}, [%4];"
                 : "=r"(r0), "=r"(r1), "=r"(r2), "=r"(r3) : "r"(addr));
}
__device__ __forceinline__ void mma16816(float* d, const uint32_t* a, uint32_t b0,
                                         uint32_t b1) {
    asm volatile(
        "mma.sync.aligned.m16n8k16.row.col.f32.bf16.bf16.f32 "
        "{%0,%1,%2,%3}, {%4,%5,%6,%7}, {%8,%9}, {%0,%1,%2,%3};"
        : "+f"(d[0]), "+f"(d[1]), "+f"(d[2]), "+f"(d[3])
        : "r"(a[0]), "r"(a[1]), "r"(a[2]), "r"(a[3]), "r"(b0), "r"(b1));
}

// ---------------- init ----------------
__global__ void k_init() {
    int i = threadIdx.x;
    if (i < KDIM) { g_col[i] = 0.0f; g_diag[i] = 0.0f; }
    if (i == 0) { g_sA = 0.0f; g_hpart = 0.0f; }
}

// ---------------- convert C (fp32) -> g_Cb (bf16), same layout ----------------
__global__ void __launch_bounds__(256) k_prep(const float* __restrict__ C) {
    size_t base = ((size_t)blockIdx.x * 256 + threadIdx.x) * 16;
    const float4* src = reinterpret_cast<const float4*>(C + base);
    uint32_t o[8];
#pragma unroll
    for (int q = 0; q < 4; ++q) {
        float4 v = __ldg(&src[q]);
        o[q * 2 + 0] = cvt_bf2(make_float2(v.x, v.y));
        o[q * 2 + 1] = cvt_bf2(make_float2(v.z, v.w));
    }
    uint4* dst = reinterpret_cast<uint4*>(g_Cb + base);
    dst[0] = make_uint4(o[0], o[1], o[2], o[3]);
    dst[1] = make_uint4(o[4], o[5], o[6], o[7]);
}

// ---------------- main GEMM: M = A@C via mma.sync, fused reductions ----------------
__global__ void __launch_bounds__(256) k_gemm(const float* __restrict__ A,
                                              const float* __restrict__ C) {
    extern __shared__ __align__(1024) char smem[];
    __shared__ float scol[KDIM], sdiag[KDIM];

    const int tid = threadIdx.x, lane = tid & 31, wid = tid >> 5;
    const int wm = wid & 3, wn = wid >> 2;           // 4 M-warps x 2 N-warps
    const int blockRow = blockIdx.x * BM;
    const uint32_t su = smem_u32(smem);

    if (tid < KDIM) { scol[tid] = 0.0f; sdiag[tid] = 0.0f; }

    // ---- cp.async chunk mapping (2 A-chunks + 2 B-chunks per thread) ----
    // A tile: 64 rows x 32 fp32, row = 128B = 8 chunks; swizzle: ^(r&7)<<4
    // B tile: 32 rows x 128 bf16, row = 256B = 16 chunks; swizzle: ^(k&7)<<4
    const int chA0 = tid, chA1 = tid + 256;
    const int rA0 = chA0 >> 3, cA0 = chA0 & 7;
    const int rA1 = chA1 >> 3, cA1 = chA1 & 7;
    const uint32_t soA0 = (uint32_t)(chA0 * 16) ^ ((rA0 & 7) << 4);
    const uint32_t soA1 = (uint32_t)(chA1 * 16) ^ ((rA1 & 7) << 4);
    const float* gA0 = A + (size_t)(blockRow + rA0) * N_FIX + cA0 * 4;
    const float* gA1 = A + (size_t)(blockRow + rA1) * N_FIX + cA1 * 4;

    const int kB0 = chA0 >> 4, cB0 = chA0 & 15;
    const int kB1 = chA1 >> 4, cB1 = chA1 & 15;
    const uint32_t soB0 = (uint32_t)(chA0 * 16) ^ ((kB0 & 7) << 4);
    const uint32_t soB1 = (uint32_t)(chA1 * 16) ^ ((kB1 & 7) << 4);
    const __nv_bfloat16* gB0 = g_Cb + (size_t)kB0 * KDIM + cB0 * 8;
    const __nv_bfloat16* gB1 = g_Cb + (size_t)kB1 * KDIM + cB1 * 8;

    // ---- fragment smem offsets ----
    const int r0 = wm * 16 + (lane >> 2);
    const int cb = (lane & 3) * 2;
    uint32_t aoff[2][4];
#pragma unroll
    for (int kq = 0; kq < 2; ++kq) {
        int cc = kq * 16 + cb;
#pragma unroll
        for (int q = 0; q < 4; ++q) {
            int rr = r0 + ((q & 1) ? 8 : 0);
            int c2 = cc + ((q & 2) ? 8 : 0);
            uint32_t off = (uint32_t)(rr * 128 + c2 * 4);
            aoff[kq][q] = off ^ ((rr & 7) << 4);
        }
    }
    uint32_t boff[4];
    {
        const int mM = lane >> 3, iR = lane & 7;
        const int kkb = (mM & 1) * 8 + iR;
#pragma unroll
        for (int g = 0; g < 4; ++g) {
            int nn = wn * 64 + g * 16 + (mM >> 1) * 8;
            uint32_t off = (uint32_t)(kkb * 256 + nn * 2);
            boff[g] = off ^ ((kkb & 7) << 4);
        }
    }

    float acc[8][4];
#pragma unroll
    for (int t = 0; t < 8; ++t)
#pragma unroll
        for (int e = 0; e < 4; ++e) acc[t][e] = 0.0f;
    float dr0 = 0.0f, dr1 = 0.0f;

    // ---- prologue: fill STAGES-1 stages ----
#pragma unroll
    for (int s = 0; s < STAGES - 1; ++s) {
        uint32_t sb = su + s * STAGE_BYTES;
        size_t kf = (size_t)s * BK;
        cp16(sb + soA0, gA0 + kf);
        cp16(sb + soA1, gA1 + kf);
        cp16(sb + 8192 + soB0, gB0 + kf * KDIM);
        cp16(sb + 8192 + soB1, gB1 + kf * KDIM);
        CP_COMMIT();
    }

    // ---- main loop ----
    for (int it = 0; it < NITER; ++it) {
        CP_WAIT2();
        __syncthreads();
        const char* stp = smem + (it & (STAGES - 1)) * STAGE_BYTES;
        const uint32_t bbase = su + (uint32_t)((it & (STAGES - 1)) * STAGE_BYTES) + 8192;

#pragma unroll
        for (int kq = 0; kq < 2; ++kq) {
            float2 fA[4];
#pragma unroll
            for (int q = 0; q < 4; ++q)
                fA[q] = *reinterpret_cast<const float2*>(stp + aoff[kq][q]);
            dr0 += (fA[0].x + fA[0].y) + (fA[2].x + fA[2].y);
            dr1 += (fA[1].x + fA[1].y) + (fA[3].x + fA[3].y);
            uint32_t ra[4];
#pragma unroll
            for (int q = 0; q < 4; ++q) ra[q] = cvt_bf2(fA[q]);

#pragma unroll
            for (int g = 0; g < 4; ++g) {
                uint32_t b0, b1, b2, b3;
                ldmx4t(b0, b1, b2, b3, bbase + kq * 4096 + boff[g]);
                mma16816(acc[2 * g], ra, b0, b1);
                mma16816(acc[2 * g + 1], ra, b2, b3);
            }
        }

        int nxt = it + (STAGES - 1);
        if (nxt < NITER) {
            uint32_t sb = su + (nxt & (STAGES - 1)) * STAGE_BYTES;
            size_t kf = (size_t)nxt * BK;
            cp16(sb + soA0, gA0 + kf);
            cp16(sb + soA1, gA1 + kf);
            cp16(sb + 8192 + soB0, gB0 + kf * KDIM);
            cp16(sb + 8192 + soB1, gB1 + kf * KDIM);
        }
        CP_COMMIT();
    }

    // ---- row sums of A (exact fp32; only wn==0 warps, no double count) ----
    if (wn == 0) {
        float s0 = dr0, s1 = dr1;
        s0 += __shfl_xor_sync(0xffffffffu, s0, 1);
        s0 += __shfl_xor_sync(0xffffffffu, s0, 2);
        s1 += __shfl_xor_sync(0xffffffffu, s1, 1);
        s1 += __shfl_xor_sync(0xffffffffu, s1, 2);
        if ((lane & 3) == 0) {
            g_d[blockRow + r0] = s0;
            g_d[blockRow + r0 + 8] = s1;
        }
    }

    // ---- fused epilogue: colsum(M) and diag = sum_i C[i][j]*M[i][j] ----
#pragma unroll
    for (int t = 0; t < 8; ++t) {
        const int cbase = wn * 64 + t * 8 + cb;
        const int row = blockRow + r0;
        float2 c0 = *reinterpret_cast<const float2*>(C + (size_t)row * KDIM + cbase);
        float2 c1 = *reinterpret_cast<const float2*>(C + (size_t)(row + 8) * KDIM + cbase);
        float cs0 = acc[t][0] + acc[t][2];
        float cs1 = acc[t][1] + acc[t][3];
        float ds0 = c0.x * acc[t][0] + c1.x * acc[t][2];
        float ds1 = c0.y * acc[t][1] + c1.y * acc[t][3];
#pragma unroll
        for (int o = 4; o <= 16; o <<= 1) {
            cs0 += __shfl_xor_sync(0xffffffffu, cs0, o);
            cs1 += __shfl_xor_sync(0xffffffffu, cs1, o);
            ds0 += __shfl_xor_sync(0xffffffffu, ds0, o);
            ds1 += __shfl_xor_sync(0xffffffffu, ds1, o);
        }
        if ((lane >> 2) == 0) {  // lanes 0..3
            atomicAdd(&scol[cbase], cs0);
            atomicAdd(&scol[cbase + 1], cs1);
            atomicAdd(&sdiag[cbase], ds0);
            atomicAdd(&sdiag[cbase + 1], ds1);
        }
    }
    __syncthreads();
    if (tid < KDIM) {
        atomicAdd(&g_col[tid], scol[tid]);
        atomicAdd(&g_diag[tid], sdiag[tid]);
    }
}

// ---------------- h_part + sA ----------------
__global__ void __launch_bounds__(256) k_hpart(const float* __restrict__ H) {
    const int tid = threadIdx.x;
    const int row = blockIdx.x * 128 + (tid >> 1);
    const int ch = (tid & 1) * 64;
    const float4* hp = reinterpret_cast<const float4*>(H + (size_t)row * KDIM + ch);
    float h2 = 0.0f;
#pragma unroll
    for (int q = 0; q < 16; ++q) {
        float4 v = __ldg(&hp[q]);
        h2 += v.x * v.x + v.y * v.y + v.z * v.z + v.w * v.w;
    }
    h2 += __shfl_xor_sync(0xffffffffu, h2, 1);
    float dval = 0.0f, hc = 0.0f;
    if ((tid & 1) == 0) {
        dval = g_d[row];
        hc = dval * h2;
    }
    __shared__ float s1[256], s2[256];
    s1[tid] = hc; s2[tid] = dval;
    __syncthreads();
    for (int s = 128; s > 0; s >>= 1) {
        if (tid < s) { s1[tid] += s1[tid + s]; s2[tid] += s2[tid + s]; }
        __syncthreads();
    }
    if (tid == 0) {
        atomicAdd(&g_hpart, s1[0]);
        atomicAdd(&g_sA, s2[0]);
    }
}

// ---------------- final scalar epilogue ----------------
__global__ void k_final(const float* papra, const int* flag, float* out, int out_size) {
    const int tid = threadIdx.x;  // 128 threads
    float sA = g_sA;
    float t = g_diag[tid] * log2f(g_col[tid] / sA + 1e-40f);
    __shared__ float s[128];
    s[tid] = t;
    __syncthreads();
    for (int st = 64; st > 0; st >>= 1) {
        if (tid < st) s[tid] += s[tid + st];
        __syncthreads();
    }
    if (tid == 0) {
        float total = s[0] / sA;
        float hp = g_hpart;
        int fl = flag ? *flag : 20;
        float pw = papra ? *papra : 1.0f;
        if (fl > 10) total += pw * hp;
        out[0] = total;
        if (out_size > 1) out[1] = hp;
    }
}

extern "C" void kernel_launch(void* const* d_in, const int* in_sizes, int n_in,
                              void* d_out, int out_size) {
    const float* A = (const float*)d_in[0];
    const float* C = (const float*)d_in[1];
    const float* H = (const float*)d_in[2];
    const float* papra = (n_in > 3) ? (const float*)d_in[3] : nullptr;
    const int* flag = (n_in > 4) ? (const int*)d_in[4] : nullptr;

    cudaFuncSetAttribute(k_gemm, cudaFuncAttributeMaxDynamicSharedMemorySize, SMEM_BYTES);

    k_init<<<1, 256>>>();
    k_prep<<<(N_FIX * KDIM) / (256 * 16), 256>>>(C);
    k_gemm<<<N_FIX / BM, 256, SMEM_BYTES>>>(A, C);
    k_hpart<<<N_FIX / 128, 256>>>(H);
    k_final<<<1, 128>>>(papra, flag, (float*)d_out, out_size);
}